// round 15
// baseline (speedup 1.0000x reference)
#include <cuda_runtime.h>
#include <cstdint>

#define D 64                 // D_IN == D_OUT == 64
#define MAX_NODES 100000

// Scratch accumulator for the scatter phase (25.6 MB). __device__ global: no allocation.
__device__ float g_agg[(size_t)MAX_NODES * D];
// Runtime-detected edge_index dtype: 1 = int64, 0 = int32.
__device__ int g_idx_is64;

// ---------------------------------------------------------------------------
// Kernel 0: detect edge_index dtype. If the data is really int64 (values
// < N_NODES), all int64 interpretations of the first 16 entries are small.
// If it is int32, the hi-word of each 8-byte pair is another random index in
// [0, 100000) — nonzero with p ~ 1-1e-5 each, so 16 checks are conclusive.
// Runs every launch, deterministic, graph-capturable.
// ---------------------------------------------------------------------------
__global__ void detect_dtype_kernel(const unsigned long long* __restrict__ ei64,
                                    int N) {
    bool is64 = true;
    for (int i = 0; i < 16; i++) {
        if (ei64[i] >= (unsigned long long)N) { is64 = false; break; }
    }
    g_idx_is64 = is64 ? 1 : 0;
}

// ---------------------------------------------------------------------------
// Kernel 1: zero the accumulator (g_agg persists across graph replays).
// ---------------------------------------------------------------------------
__global__ void zero_agg_kernel(int n4) {
    int t = blockIdx.x * blockDim.x + threadIdx.x;
    if (t < n4) {
        reinterpret_cast<float4*>(g_agg)[t] = make_float4(0.f, 0.f, 0.f, 0.f);
    }
}

// ---------------------------------------------------------------------------
// Kernel 2: edge scatter. 4 threads per edge, each handles 64 bytes
// (4×float4) of the source row, reducing into the destination row with
// red.global.add.v4.f32 (fire-and-forget vector reduction, no return dep).
// Index loads branch uniformly on the detected dtype; indices are bounds-
// guarded so a bad index can never fault.
// ---------------------------------------------------------------------------
__global__ void scatter_kernel(const float* __restrict__ x,
                               const void* __restrict__ ei_raw,
                               int E, int N) {
    int t = blockIdx.x * blockDim.x + threadIdx.x;
    if (t >= E * 4) return;
    int e = t >> 2;          // edge id
    int q = t & 3;           // quarter of the 64-float row

    int src, dst;
    if (g_idx_is64) {
        const long long* ei = (const long long*)ei_raw;
        src = (int)__ldg(ei + e);
        dst = (int)__ldg(ei + E + e);
    } else {
        const int* ei = (const int*)ei_raw;
        src = __ldg(ei + e);
        dst = __ldg(ei + E + e);
    }
    if ((unsigned)src >= (unsigned)N || (unsigned)dst >= (unsigned)N) return;

    const float4* xs = reinterpret_cast<const float4*>(x + (size_t)src * D) + q * 4;
    float* dp = g_agg + (size_t)dst * D + q * 16;

#pragma unroll
    for (int i = 0; i < 4; i++) {
        float4 v = xs[i];
        asm volatile(
            "red.global.add.v4.f32 [%0], {%1, %2, %3, %4};"
            :: "l"(dp + i * 4), "f"(v.x), "f"(v.y), "f"(v.z), "f"(v.w)
            : "memory");
    }
}

// ---------------------------------------------------------------------------
// Kernel 3: mean + GEMM epilogue.  out[n,:] = (agg[n,:] / deg[n]) @ W^T + b
// One node per thread; W staged transposed in smem (broadcast LDS.128);
// x-row in 64 registers; inner k-loop fully unrolled.
// ---------------------------------------------------------------------------
__global__ void __launch_bounds__(128)
mean_gemm_kernel(const float* __restrict__ deg,
                 const float* __restrict__ W,
                 const float* __restrict__ b,
                 float* __restrict__ out,
                 int N) {
    __shared__ float Wt[D * D];   // Wt[k*64 + j] = W[j*64 + k]
    __shared__ float bs[D];

    int tid = threadIdx.x;
    for (int i = tid; i < D * D; i += blockDim.x) {
        int j = i >> 6, k = i & 63;
        Wt[k * D + j] = W[i];
    }
    if (tid < D) bs[tid] = b[tid];
    __syncthreads();

    int n = blockIdx.x * blockDim.x + tid;
    if (n >= N) return;

    float inv = 1.0f / deg[n];

    float xr[D];
    const float4* xrow = reinterpret_cast<const float4*>(g_agg + (size_t)n * D);
#pragma unroll
    for (int i = 0; i < D / 4; i++) {
        float4 v = xrow[i];
        xr[4 * i + 0] = v.x * inv;
        xr[4 * i + 1] = v.y * inv;
        xr[4 * i + 2] = v.z * inv;
        xr[4 * i + 3] = v.w * inv;
    }

    float4* orow = reinterpret_cast<float4*>(out + (size_t)n * D);
    for (int j4 = 0; j4 < D / 4; j4++) {
        float4 acc = *reinterpret_cast<const float4*>(&bs[j4 * 4]);
#pragma unroll
        for (int k = 0; k < D; k++) {
            float4 w = *reinterpret_cast<const float4*>(&Wt[k * D + j4 * 4]);
            acc.x = fmaf(xr[k], w.x, acc.x);
            acc.y = fmaf(xr[k], w.y, acc.y);
            acc.z = fmaf(xr[k], w.z, acc.z);
            acc.w = fmaf(xr[k], w.w, acc.w);
        }
        orow[j4] = acc;
    }
}

// ---------------------------------------------------------------------------
// Launch. Inputs (metadata order): x[f32 N*64], edge_index[2*E int32 or
// int64 — runtime detected], node_degrees[f32 N], W[f32 64*64], b[f32 64].
// Output: f32 N*64.
// ---------------------------------------------------------------------------
extern "C" void kernel_launch(void* const* d_in, const int* in_sizes, int n_in,
                              void* d_out, int out_size) {
    const float* x   = (const float*)d_in[0];
    const void*  ei  = d_in[1];
    const float* deg = (const float*)d_in[2];
    const float* W   = (const float*)d_in[3];
    const float* b   = (const float*)d_in[4];
    float*       out = (float*)d_out;

    const int E = in_sizes[1] / 2;
    const int N = in_sizes[2];

    // 0) detect edge_index dtype (1 thread; reads 128B either way — safe,
    //    since the buffer holds at least 2E*4 = 8 MB).
    detect_dtype_kernel<<<1, 1>>>((const unsigned long long*)ei, N);

    // 1) zero the accumulator
    {
        int n4 = N * (D / 4);
        int threads = 256;
        int blocks = (n4 + threads - 1) / threads;
        zero_agg_kernel<<<blocks, threads>>>(n4);
    }

    // 2) scatter-add x[src] into g_agg[dst]
    {
        int total = E * 4;
        int threads = 256;
        int blocks = (total + threads - 1) / threads;
        scatter_kernel<<<blocks, threads>>>(x, ei, E, N);
    }

    // 3) mean + GEMM + bias
    {
        int threads = 128;
        int blocks = (N + threads - 1) / threads;
        mean_gemm_kernel<<<blocks, threads>>>(deg, W, b, out, N);
    }
}